// round 6
// baseline (speedup 1.0000x reference)
#include <cuda_runtime.h>
#include <math_constants.h>

#define GRID_SZ 64
#define HALF 2
#define CCH 256
#define KPT 16
#define NB 256
#define KM_TOTAL_I (256 * 256 * 4096)   // 2^28 floats, fits int32

__global__ __launch_bounds__(256, 4)
void pose_kernel(const float* __restrict__ keymap,
                 const float* __restrict__ first_keys,
                 const float* __restrict__ prev_keys,
                 const int*   __restrict__ prev_kps,
                 float* __restrict__ out)
{
    // one block per (b,k)
    const int bk   = blockIdx.x;
    const int tid  = threadIdx.x;
    const int lane = tid & 31;
    const int warp = tid >> 5;
    const int h    = tid & 1;     // which float4 half of the 8-float window
    const int cp   = tid >> 1;    // channel pair 0..127
    const int b    = bk >> 4;

    const int px = prev_kps[bk * 2 + 0];
    const int py = prev_kps[bk * 2 + 1];

    // 16B-aligned 8-float region [a0, a0+8) covers window cols [px-2, px+2]
    const int a0 = (px - HALF) & ~3;

    const int c0 = 2 * cp;
    const float fk0 = first_keys[bk * CCH + c0];
    const float fk1 = first_keys[bk * CCH + c0 + 1];
    const float pk0 = prev_keys [bk * CCH + c0];
    const float pk1 = prev_keys [bk * CCH + c0 + 1];

    const int base0 = ((b * CCH + c0) << 12) + a0 + 4 * h;   // plane*4096 + col

    float acc[5][4];
    #pragma unroll
    for (int i = 0; i < 5; i++)
        #pragma unroll
        for (int w = 0; w < 4; w++)
            acc[i][w] = 0.0f;

    // R2 loop shape: interleaved load + consume; unconditional clamped loads.
    // Garbage values (invalid rows / out-of-window slots) only reach cells
    // that are masked to +inf below.
    #pragma unroll
    for (int q = 0; q < 2; q++) {
        const float fk = q ? fk1 : fk0;
        const float pk = q ? pk1 : pk0;
        const int planeBase = base0 + (q << 12);
        #pragma unroll
        for (int i = 0; i < 5; i++) {
            const int gy = py + i - HALF;
            int idx = planeBase + gy * GRID_SZ;
            idx = max(idx, 0);
            idx = min(idx, KM_TOTAL_I - 4);
            const float4 f4 = __ldg((const float4*)(keymap + idx));

            float a, d;
            a = f4.x - fk; d = f4.x - pk; acc[i][0] += 0.25f*a*a + 0.75f*d*d;
            a = f4.y - fk; d = f4.y - pk; acc[i][1] += 0.25f*a*a + 0.75f*d*d;
            a = f4.z - fk; d = f4.z - pk; acc[i][2] += 0.25f*a*a + 0.75f*d*d;
            a = f4.w - fk; d = f4.w - pk; acc[i][3] += 0.25f*a*a + 0.75f*d*d;
        }
    }

    // parity-preserving warp reduction: lane0 keeps h=0 sums, lane1 keeps h=1
    __shared__ float part[8][2][20];
    #pragma unroll
    for (int i = 0; i < 5; i++) {
        #pragma unroll
        for (int w = 0; w < 4; w++) {
            float v = acc[i][w];
            v += __shfl_down_sync(0xFFFFFFFFu, v, 16);
            v += __shfl_down_sync(0xFFFFFFFFu, v, 8);
            v += __shfl_down_sync(0xFFFFFFFFu, v, 4);
            v += __shfl_down_sync(0xFFFFFFFFu, v, 2);
            if (lane < 2) part[warp][lane][i * 4 + w] = v;
        }
    }
    __syncthreads();

    __shared__ float dmap[25];
    if (tid < 25) {
        const int i = tid / 5;
        const int j = tid % 5;
        const int r    = (px - HALF) - a0;   // 0..3
        const int w    = r + j;              // 0..7
        const int wh   = w >> 2;
        const int slot = i * 4 + (w & 3);
        float s = 0.0f;
        #pragma unroll
        for (int wp = 0; wp < 8; wp++) s += part[wp][wh][slot];

        const int gx = px + j - HALF;
        const int gy = py + i - HALF;
        const bool valid = ((unsigned)gx < GRID_SZ) && ((unsigned)gy < GRID_SZ);

        // weight map (window-local coords, replicating reference)
        const int x0 = max(px - HALF, 0);
        const int y0 = max(py - HALF, 0);
        const int Wd = min(px + HALF, GRID_SZ - 1) - x0 + 1;
        const int Hd = min(py + HALF, GRID_SZ - 1) - y0 + 1;
        const int tx = px - x0, ty = py - y0;
        const int wx = gx - x0, wy = gy - y0;

        const int xl1 = max(tx - 1, 0), xr1 = min(tx + 1, Wd - 1);
        const int yu1 = max(ty - 1, 0), yd1 = min(ty + 1, Hd - 1);
        const bool in_x1 = (wx >= xl1) && (wx <= xr1);
        const bool in_y1 = (wy >= yu1) && (wy <= yd1);
        const bool ring1 = (((wx == xl1) || (wx == xr1)) && in_y1) ||
                           (((wy == yu1) || (wy == yd1)) && in_x1);
        float wgt = ring1 ? 0.6f : 0.5f;

        const int xl2 = max(tx - 2, 0), xr2 = min(tx + 2, Wd - 1);
        const int yu2 = max(ty - 2, 0), yd2 = min(ty + 2, Hd - 1);
        const bool in_x2 = (wx >= xl2) && (wx <= xr2);
        const bool in_y2 = (wy >= yu2) && (wy <= yd2);
        const bool l_skip = (xl1 == 0), r_skip = (xr1 == Wd - 1);
        const bool u_skip = (yu1 == 0), d_skip = (yd1 == Hd - 1);
        const bool ring2 = (!l_skip && (wx == xl2) && in_y2) ||
                           (!r_skip && (wx == xr2) && in_y2) ||
                           (!u_skip && (wy == yu2) && in_x2) ||
                           (!d_skip && (wy == yd2) && in_x2);
        if (ring2) wgt = 0.7f;

        dmap[tid] = valid ? (wgt * s) : CUDART_INF_F;
    }
    __syncthreads();

    if (tid == 0) {
        float best = dmap[0];
        int bi = 0;
        #pragma unroll
        for (int i = 1; i < 25; i++) {
            const float v = dmap[i];
            if (v < best) { best = v; bi = i; }
        }
        const int ox = bi % 5 - HALF;
        const int oy = bi / 5 - HALF;
        out[bk * 2 + 0] = (float)(px + ox);
        out[bk * 2 + 1] = (float)(py + oy);
        out[NB * KPT * 2 + bk] = best;
    }
}

extern "C" void kernel_launch(void* const* d_in, const int* in_sizes, int n_in,
                              void* d_out, int out_size)
{
    const float* keymap     = (const float*)d_in[0];
    const float* first_keys = (const float*)d_in[1];
    const float* prev_keys  = (const float*)d_in[2];
    const int*   prev_kps   = (const int*)d_in[3];
    float* out = (float*)d_out;

    pose_kernel<<<NB * KPT, 256>>>(keymap, first_keys, prev_keys, prev_kps, out);
}

// round 7
// speedup vs baseline: 1.0481x; 1.0481x over previous
#include <cuda_runtime.h>
#include <math_constants.h>

#define GRID_SZ 64
#define HALF 2
#define CCH 256
#define KPT 16
#define NB 256
#define KM_TOTAL (256LL * 256LL * 4096LL)

__global__ __launch_bounds__(256, 5)
void pose_kernel(const float* __restrict__ keymap,
                 const float* __restrict__ first_keys,
                 const float* __restrict__ prev_keys,
                 const int*   __restrict__ prev_kps,
                 float* __restrict__ out)
{
    // one block per (b,k)
    const int bk   = blockIdx.x;
    const int tid  = threadIdx.x;
    const int lane = tid & 31;
    const int warp = tid >> 5;
    const int h    = tid & 1;     // which float4 half of the 8-float window
    const int cp   = tid >> 1;    // channel pair 0..127
    const int b    = bk / KPT;

    const int px = prev_kps[bk * 2 + 0];
    const int py = prev_kps[bk * 2 + 1];

    // 8-float aligned region [a0, a0+8) always covers window cols [px-2, px+2]
    const int a0 = (px - HALF) & ~3;
    const int r  = (px - HALF) - a0;          // 0..3, uniform per block

    const int c0 = 2 * cp;
    const float fk0 = first_keys[bk * CCH + c0];
    const float fk1 = first_keys[bk * CCH + c0 + 1];
    const float pk0 = prev_keys [bk * CCH + c0];
    const float pk1 = prev_keys [bk * CCH + c0 + 1];

    float acc[5][4];
    #pragma unroll
    for (int i = 0; i < 5; i++)
        #pragma unroll
        for (int w = 0; w < 4; w++)
            acc[i][w] = 0.0f;

    #pragma unroll
    for (int q = 0; q < 2; q++) {
        const float fk = q ? fk1 : fk0;
        const float pk = q ? pk1 : pk0;
        const long long planeBase = ((long long)(b * CCH + c0 + q)) << 12; // *4096
        #pragma unroll
        for (int i = 0; i < 5; i++) {
            const int gy = py + i - HALF;
            const bool vy = ((unsigned)gy < GRID_SZ);
            long long idx = planeBase + (long long)(gy * GRID_SZ + a0 + 4 * h);
            // clamp (16B-aligned endpoints); clamped values only reach invalid cells
            if (idx < 0) idx = 0;
            if (idx > KM_TOTAL - 4) idx = KM_TOTAL - 4;
            float4 f4 = make_float4(0.f, 0.f, 0.f, 0.f);
            if (vy) f4 = __ldg((const float4*)(keymap + idx));

            float a, d;
            a = f4.x - fk; d = f4.x - pk; acc[i][0] += 0.25f*a*a + 0.75f*d*d;
            a = f4.y - fk; d = f4.y - pk; acc[i][1] += 0.25f*a*a + 0.75f*d*d;
            a = f4.z - fk; d = f4.z - pk; acc[i][2] += 0.25f*a*a + 0.75f*d*d;
            a = f4.w - fk; d = f4.w - pk; acc[i][3] += 0.25f*a*a + 0.75f*d*d;
        }
    }

    // parity-preserving warp reduction: lane0 = sums for h=0, lane1 = h=1
    __shared__ float part[8][2][20];
    #pragma unroll
    for (int i = 0; i < 5; i++) {
        #pragma unroll
        for (int w = 0; w < 4; w++) {
            float v = acc[i][w];
            v += __shfl_down_sync(0xFFFFFFFFu, v, 16);
            v += __shfl_down_sync(0xFFFFFFFFu, v, 8);
            v += __shfl_down_sync(0xFFFFFFFFu, v, 4);
            v += __shfl_down_sync(0xFFFFFFFFu, v, 2);
            if (lane < 2) part[warp][lane][i * 4 + w] = v;
        }
    }
    __syncthreads();

    __shared__ float dmap[25];
    if (tid < 25) {
        const int i = tid / 5;
        const int j = tid % 5;
        const int w    = r + j;        // 0..7
        const int wh   = w >> 2;
        const int slot = i * 4 + (w & 3);
        float s = 0.0f;
        #pragma unroll
        for (int wp = 0; wp < 8; wp++) s += part[wp][wh][slot];

        const int gx = px + j - HALF;
        const int gy = py + i - HALF;
        const bool valid = ((unsigned)gx < GRID_SZ) && ((unsigned)gy < GRID_SZ);

        // weight map (window-local coords, replicating reference)
        const int x0 = max(px - HALF, 0);
        const int y0 = max(py - HALF, 0);
        const int Wd = min(px + HALF, GRID_SZ - 1) - x0 + 1;
        const int Hd = min(py + HALF, GRID_SZ - 1) - y0 + 1;
        const int tx = px - x0, ty = py - y0;
        const int wx = gx - x0, wy = gy - y0;

        const int xl1 = max(tx - 1, 0), xr1 = min(tx + 1, Wd - 1);
        const int yu1 = max(ty - 1, 0), yd1 = min(ty + 1, Hd - 1);
        const bool in_x1 = (wx >= xl1) && (wx <= xr1);
        const bool in_y1 = (wy >= yu1) && (wy <= yd1);
        const bool ring1 = (((wx == xl1) || (wx == xr1)) && in_y1) ||
                           (((wy == yu1) || (wy == yd1)) && in_x1);
        float wgt = ring1 ? 0.6f : 0.5f;

        const int xl2 = max(tx - 2, 0), xr2 = min(tx + 2, Wd - 1);
        const int yu2 = max(ty - 2, 0), yd2 = min(ty + 2, Hd - 1);
        const bool in_x2 = (wx >= xl2) && (wx <= xr2);
        const bool in_y2 = (wy >= yu2) && (wy <= yd2);
        const bool l_skip = (xl1 == 0), r_skip = (xr1 == Wd - 1);
        const bool u_skip = (yu1 == 0), d_skip = (yd1 == Hd - 1);
        const bool ring2 = (!l_skip && (wx == xl2) && in_y2) ||
                           (!r_skip && (wx == xr2) && in_y2) ||
                           (!u_skip && (wy == yu2) && in_x2) ||
                           (!d_skip && (wy == yd2) && in_x2);
        if (ring2) wgt = 0.7f;

        dmap[tid] = valid ? (wgt * s) : CUDART_INF_F;
    }
    __syncthreads();

    if (tid == 0) {
        float best = dmap[0];
        int bi = 0;
        #pragma unroll
        for (int i = 1; i < 25; i++) {
            const float v = dmap[i];
            if (v < best) { best = v; bi = i; }
        }
        const int ox = bi % 5 - HALF;
        const int oy = bi / 5 - HALF;
        out[bk * 2 + 0] = (float)(px + ox);
        out[bk * 2 + 1] = (float)(py + oy);
        out[NB * KPT * 2 + bk] = best;
    }
}

extern "C" void kernel_launch(void* const* d_in, const int* in_sizes, int n_in,
                              void* d_out, int out_size)
{
    const float* keymap     = (const float*)d_in[0];
    const float* first_keys = (const float*)d_in[1];
    const float* prev_keys  = (const float*)d_in[2];
    const int*   prev_kps   = (const int*)d_in[3];
    float* out = (float*)d_out;

    pose_kernel<<<NB * KPT, 256>>>(keymap, first_keys, prev_keys, prev_kps, out);
}